// round 12
// baseline (speedup 1.0000x reference)
#include <cuda_runtime.h>
#include <cuda.h>
#include <cuda_bf16.h>
#include <math.h>
#include <stdint.h>

// Problem constants
#define T_TOK   2048
#define D_MODEL 2048
#define QKV_N   3072
#define FF_N    8192
#define SEQ     1024
#define NHEAD   32
#define NKV     8
#define HDIM    64

// ---------------------------------------------------------------------------
// Scratch (allocation-free: device globals)
// ---------------------------------------------------------------------------
__device__ float g_h   [T_TOK * (size_t)D_MODEL];
__device__ float g_qkv [T_TOK * (size_t)QKV_N];
__device__ float g_ctx [T_TOK * (size_t)D_MODEL];
__device__ float g_attn[T_TOK * (size_t)D_MODEL];
__device__ float g_ff  [T_TOK * (size_t)FF_N];

// ---------------------------------------------------------------------------
// Device helpers
// ---------------------------------------------------------------------------
__device__ __forceinline__ uint32_t smem_u32(const void* p) {
    uint32_t a;
    asm("{ .reg .u64 t; cvta.to.shared.u64 t, %1; cvt.u32.u64 %0, t; }"
        : "=r"(a) : "l"(p));
    return a;
}
__device__ __forceinline__ void mbar_init(uint32_t addr, uint32_t cnt) {
    asm volatile("mbarrier.init.shared.b64 [%0], %1;" :: "r"(addr), "r"(cnt) : "memory");
}
__device__ __forceinline__ void mbar_expect(uint32_t addr, uint32_t bytes) {
    asm volatile("mbarrier.arrive.expect_tx.shared.b64 _, [%0], %1;"
                 :: "r"(addr), "r"(bytes) : "memory");
}
__device__ __forceinline__ void mbar_wait(uint32_t addr, int parity) {
    uint32_t done;
    asm volatile("{\n\t.reg .pred p;\n\t"
        "mbarrier.try_wait.parity.acquire.cta.shared::cta.b64 p, [%1], %2;\n\t"
        "selp.b32 %0, 1, 0, p;\n\t}"
        : "=r"(done) : "r"(addr), "r"((uint32_t)parity) : "memory");
    while (!done) {
        asm volatile("{\n\t.reg .pred p;\n\t"
            "mbarrier.try_wait.parity.acquire.cta.shared::cta.b64 p, [%1], %2, 0x989680;\n\t"
            "selp.b32 %0, 1, 0, p;\n\t}"
            : "=r"(done) : "r"(addr), "r"((uint32_t)parity) : "memory");
    }
}
__device__ __forceinline__ void tma2d(uint32_t smem, const CUtensorMap* tm,
                                      int cx, int cy, uint32_t mbar) {
    asm volatile(
        "cp.async.bulk.tensor.2d.shared::cta.global.tile.mbarrier::complete_tx::bytes "
        "[%0], [%1, {%2, %3}], [%4];"
        :: "r"(smem), "l"(tm), "r"(cx), "r"(cy), "r"(mbar) : "memory");
}
__device__ __forceinline__ uint32_t f2tf(float f) {
    uint32_t o;
    asm("cvt.rna.tf32.f32 %0, %1;" : "=r"(o) : "f"(f));
    return o;
}
__device__ __forceinline__ void mma_tf32(float* c, const uint32_t* a, const uint32_t* b) {
    asm volatile(
        "mma.sync.aligned.m16n8k8.row.col.f32.tf32.tf32.f32 "
        "{%0,%1,%2,%3}, {%4,%5,%6,%7}, {%8,%9}, {%0,%1,%2,%3};"
        : "+f"(c[0]), "+f"(c[1]), "+f"(c[2]), "+f"(c[3])
        : "r"(a[0]), "r"(a[1]), "r"(a[2]), "r"(a[3]), "r"(b[0]), "r"(b[1]));
}
// SW128 swizzle for 128B rows of fp32 (32 floats): 16B chunk ^= row&7
__device__ __forceinline__ int swidx(int row, int col) {
    return row * 32 + ((((col >> 2) ^ row) & 7) << 2) + (col & 3);
}
__device__ __forceinline__ float gelu_tanh(float v) {
    float v3 = v * v * v;
    return 0.5f * v * (1.f + tanhf(0.7978845608028654f * (v + 0.044715f * v3)));
}

// ---------------------------------------------------------------------------
// tf32 HMMA GEMM: C[M,N] = A[M,K] @ B[N,K]^T + bias  (exact R9 structure)
// 128x128 CTA tile, BK=32, 4 warps (64x64 each), TMA double-buffered SW128.
// MODE 0: fp32 C    MODE 1: gelu fp32 C    MODE 2: fp32 C + R1 + R2
// ---------------------------------------------------------------------------
#define TILE_BYTES 16384
#define STAGE_TX   32768
#define GSMEM (1024 + 1024 + 4 * TILE_BYTES)

template<int MODE>
__global__ __launch_bounds__(128) void hmma_gemm(
    const __grid_constant__ CUtensorMap tmA,
    const __grid_constant__ CUtensorMap tmB,
    const float* __restrict__ bias, float* __restrict__ C,
    const float* __restrict__ R1, const float* __restrict__ R2,
    int N, int K)
{
    extern __shared__ char dsm[];
    const uint32_t raw  = smem_u32(dsm);
    const uint32_t base = (raw + 1023) & ~1023u;
    const uint32_t mb   = base;
    const uint32_t offA = base + 1024;
    const uint32_t offB = offA + 2 * TILE_BYTES;
    char* smbase = dsm + (base - raw);

    const int tid  = threadIdx.x;
    const int warp = tid >> 5, lane = tid & 31;
    const int gid  = lane >> 2, tq = lane & 3;
    const int wm   = (warp & 1) * 64, wn = (warp >> 1) * 64;
    const int tm   = blockIdx.y, tn = blockIdx.x;

    if (tid == 0) { mbar_init(mb, 1); mbar_init(mb + 8, 1); }
    __syncthreads();

    float acc[4][8][4];
    #pragma unroll
    for (int mi = 0; mi < 4; mi++)
        #pragma unroll
        for (int ni = 0; ni < 8; ni++)
            #pragma unroll
            for (int r = 0; r < 4; r++) acc[mi][ni][r] = 0.f;

    const int NI = K >> 5;
    if (tid == 0) {
        mbar_expect(mb, STAGE_TX);
        tma2d(offA, &tmA, 0, tm * 128, mb);
        tma2d(offB, &tmB, 0, tn * 128, mb);
    }
    int ph[2] = {0, 0};

    for (int i = 0; i < NI; i++) {
        const int s = i & 1;
        __syncthreads();
        if (i + 1 < NI && tid == 0) {
            const int s2 = (i + 1) & 1;
            const uint32_t m2 = mb + 8 * s2;
            mbar_expect(m2, STAGE_TX);
            tma2d(offA + s2 * TILE_BYTES, &tmA, (i + 1) * 32, tm * 128, m2);
            tma2d(offB + s2 * TILE_BYTES, &tmB, (i + 1) * 32, tn * 128, m2);
        }
        mbar_wait(mb + 8 * s, ph[s]); ph[s] ^= 1;

        const float* As = (const float*)(smbase + 1024 + s * TILE_BYTES);
        const float* Bs = (const float*)(smbase + 1024 + 2 * TILE_BYTES + s * TILE_BYTES);

        #pragma unroll
        for (int ks = 0; ks < 4; ks++) {
            const int k0 = ks * 8;
            uint32_t a[4][4], b[8][2];
            #pragma unroll
            for (int mi = 0; mi < 4; mi++) {
                const int r = wm + mi * 16 + gid;
                a[mi][0] = f2tf(As[swidx(r,     k0 + tq)]);
                a[mi][1] = f2tf(As[swidx(r + 8, k0 + tq)]);
                a[mi][2] = f2tf(As[swidx(r,     k0 + tq + 4)]);
                a[mi][3] = f2tf(As[swidx(r + 8, k0 + tq + 4)]);
            }
            #pragma unroll
            for (int ni = 0; ni < 8; ni++) {
                const int n = wn + ni * 8 + gid;
                b[ni][0] = f2tf(Bs[swidx(n, k0 + tq)]);
                b[ni][1] = f2tf(Bs[swidx(n, k0 + tq + 4)]);
            }
            #pragma unroll
            for (int mi = 0; mi < 4; mi++)
                #pragma unroll
                for (int ni = 0; ni < 8; ni++)
                    mma_tf32(acc[mi][ni], a[mi], b[ni]);
        }
    }

    #pragma unroll
    for (int mi = 0; mi < 4; mi++) {
        #pragma unroll
        for (int half = 0; half < 2; half++) {
            const int m = tm * 128 + wm + mi * 16 + gid + half * 8;
            #pragma unroll
            for (int ni = 0; ni < 8; ni++) {
                const int col = tn * 128 + wn + ni * 8 + tq * 2;
                float v0 = acc[mi][ni][half * 2 + 0] + __ldg(&bias[col]);
                float v1 = acc[mi][ni][half * 2 + 1] + __ldg(&bias[col + 1]);
                if (MODE == 1) { v0 = gelu_tanh(v0); v1 = gelu_tanh(v1); }
                const size_t idx = (size_t)m * N + col;
                if (MODE == 2) {
                    v0 += R1[idx]     + R2[idx];
                    v1 += R1[idx + 1] + R2[idx + 1];
                }
                float2 o; o.x = v0; o.y = v1;
                *(float2*)(C + idx) = o;
            }
        }
    }
}

// ---------------------------------------------------------------------------
// LayerNorm
// ---------------------------------------------------------------------------
__global__ __launch_bounds__(256) void ln_kernel(
    const float* __restrict__ x, const float* __restrict__ w,
    const float* __restrict__ b, float* __restrict__ out)
{
    const int t = blockIdx.x;
    const float* xr = x + (size_t)t * D_MODEL;
    float sum = 0.f, sq = 0.f;
    for (int i = threadIdx.x; i < D_MODEL; i += 256) {
        float v = xr[i]; sum += v; sq += v * v;
    }
    #pragma unroll
    for (int o = 16; o; o >>= 1) {
        sum += __shfl_xor_sync(0xffffffffu, sum, o);
        sq  += __shfl_xor_sync(0xffffffffu, sq,  o);
    }
    __shared__ float s1[8], s2[8];
    __shared__ float mu_s, rs_s;
    const int wid = threadIdx.x >> 5, lane = threadIdx.x & 31;
    if (!lane) { s1[wid] = sum; s2[wid] = sq; }
    __syncthreads();
    if (threadIdx.x == 0) {
        float a = 0.f, c = 0.f;
        #pragma unroll
        for (int i = 0; i < 8; i++) { a += s1[i]; c += s2[i]; }
        float mu = a / D_MODEL;
        float var = c / D_MODEL - mu * mu;
        mu_s = mu; rs_s = rsqrtf(var + 1e-5f);
    }
    __syncthreads();
    const float mu = mu_s, rs = rs_s;
    float* orow = out + (size_t)t * D_MODEL;
    for (int i = threadIdx.x; i < D_MODEL; i += 256)
        orow[i] = (xr[i] - mu) * rs * w[i] + b[i];
}

// ---------------------------------------------------------------------------
// RoPE (in place on g_qkv)
// ---------------------------------------------------------------------------
__global__ void rope_kernel(float* __restrict__ qkv)
{
    const int idx = blockIdx.x * blockDim.x + threadIdx.x;
    if (idx >= T_TOK * 40 * 16) return;
    const int pair = idx & 15;
    const int head = (idx >> 4) % 40;
    const int t    = idx / (16 * 40);
    const int pos  = t & (SEQ - 1);
    const size_t row = (size_t)t * QKV_N;
    const int off = (head < NHEAD) ? head * HDIM
                                   : NHEAD * HDIM + (head - NHEAD) * HDIM;
    const float u1 = qkv[row + off + pair];
    const float u2 = qkv[row + off + 16 + pair];
    const float inv = powf(10000.f, -(float)(2 * pair) / 32.f);
    float s, c;
    sincosf((float)pos * inv, &s, &c);
    qkv[row + off + pair]      = u1 * c - u2 * s;
    qkv[row + off + 16 + pair] = u1 * s + u2 * c;
}

// ---------------------------------------------------------------------------
// tf32 MMA causal flash attention (R9 structure).
// ONE change: heavy q-tiles scheduled first (qt = gridDim.x-1-blockIdx.x).
// ---------------------------------------------------------------------------
#define AQ 68
#define ASMEM (4 * 64 * AQ * 4)

__global__ __launch_bounds__(128) void attn_mma_kernel(
    const float* __restrict__ qkv, float* __restrict__ ctx)
{
    extern __shared__ float smf[];
    float* Qs = smf;
    float* Ks = Qs + 64 * AQ;
    float* Vs = Ks + 64 * AQ;
    float* Ps = Vs + 64 * AQ;

    const int qt = gridDim.x - 1 - blockIdx.x;   // LPT: heaviest tile first
    const int h = blockIdx.y, b = blockIdx.z;
    const int tid  = threadIdx.x;
    const int warp = tid >> 5, lane = tid & 31;
    const int gid  = lane >> 2, tq = lane & 3;
    const int kvh  = h >> 2;
    const float* base = qkv + (size_t)b * SEQ * QKV_N;

    {
        const int r = tid >> 1, half = tid & 1;
        const float* src = base + (size_t)(qt * 64 + r) * QKV_N + h * HDIM + half * 32;
        float* dst = Qs + r * AQ + half * 32;
        #pragma unroll
        for (int i = 0; i < 8; i++)
            *(float4*)(dst + i * 4) = *(const float4*)(src + i * 4);
    }

    float m0 = -1e30f, m1 = -1e30f, l0 = 0.f, l1 = 0.f;
    float o[8][4];
    #pragma unroll
    for (int ni = 0; ni < 8; ni++)
        #pragma unroll
        for (int r = 0; r < 4; r++) o[ni][r] = 0.f;

    const int qrow  = warp * 16 + gid;
    const int grow0 = qt * 64 + qrow;
    const int grow1 = grow0 + 8;
    const float scale = 0.125f;

    for (int kt = 0; kt <= qt; ++kt) {
        __syncthreads();
        {
            const int r = tid >> 1, half = tid & 1;
            const float* ks = base + (size_t)(kt * 64 + r) * QKV_N
                              + NHEAD * HDIM + kvh * HDIM + half * 32;
            const float* vs = ks + NKV * HDIM;
            float* kd = Ks + r * AQ + half * 32;
            float* vd = Vs + r * AQ + half * 32;
            #pragma unroll
            for (int i = 0; i < 8; i++) {
                *(float4*)(kd + i * 4) = *(const float4*)(ks + i * 4);
                *(float4*)(vd + i * 4) = *(const float4*)(vs + i * 4);
            }
        }
        __syncthreads();

        float s[8][4];
        #pragma unroll
        for (int ni = 0; ni < 8; ni++)
            #pragma unroll
            for (int r = 0; r < 4; r++) s[ni][r] = 0.f;

        #pragma unroll
        for (int kk = 0; kk < 8; kk++) {
            const int k0 = kk * 8;
            uint32_t a[4];
            a[0] = f2tf(Qs[qrow * AQ + k0 + tq]);
            a[1] = f2tf(Qs[(qrow + 8) * AQ + k0 + tq]);
            a[2] = f2tf(Qs[qrow * AQ + k0 + tq + 4]);
            a[3] = f2tf(Qs[(qrow + 8) * AQ + k0 + tq + 4]);
            #pragma unroll
            for (int ni = 0; ni < 8; ni++) {
                uint32_t bb[2];
                bb[0] = f2tf(Ks[(ni * 8 + gid) * AQ + k0 + tq]);
                bb[1] = f2tf(Ks[(ni * 8 + gid) * AQ + k0 + tq + 4]);
                mma_tf32(s[ni], a, bb);
            }
        }

        #pragma unroll
        for (int ni = 0; ni < 8; ni++) {
            #pragma unroll
            for (int r = 0; r < 4; r++) s[ni][r] *= scale;
        }
        if (kt == qt) {
            #pragma unroll
            for (int ni = 0; ni < 8; ni++) {
                const int c0 = kt * 64 + ni * 8 + tq * 2;
                if (c0     > grow0) s[ni][0] = -1e30f;
                if (c0 + 1 > grow0) s[ni][1] = -1e30f;
                if (c0     > grow1) s[ni][2] = -1e30f;
                if (c0 + 1 > grow1) s[ni][3] = -1e30f;
            }
        }

        float r0 = -1e30f, r1 = -1e30f;
        #pragma unroll
        for (int ni = 0; ni < 8; ni++) {
            r0 = fmaxf(r0, fmaxf(s[ni][0], s[ni][1]));
            r1 = fmaxf(r1, fmaxf(s[ni][2], s[ni][3]));
        }
        r0 = fmaxf(r0, __shfl_xor_sync(0xffffffffu, r0, 1));
        r0 = fmaxf(r0, __shfl_xor_sync(0xffffffffu, r0, 2));
        r1 = fmaxf(r1, __shfl_xor_sync(0xffffffffu, r1, 1));
        r1 = fmaxf(r1, __shfl_xor_sync(0xffffffffu, r1, 2));

        const float mn0 = fmaxf(m0, r0), mn1 = fmaxf(m1, r1);
        const float c0f = __expf(m0 - mn0), c1f = __expf(m1 - mn1);
        m0 = mn0; m1 = mn1;

        float rs0 = 0.f, rs1 = 0.f;
        #pragma unroll
        for (int ni = 0; ni < 8; ni++) {
            const float p00 = __expf(s[ni][0] - mn0);
            const float p01 = __expf(s[ni][1] - mn0);
            const float p10 = __expf(s[ni][2] - mn1);
            const float p11 = __expf(s[ni][3] - mn1);
            rs0 += p00 + p01; rs1 += p10 + p11;
            float2 w0; w0.x = p00; w0.y = p01;
            float2 w1; w1.x = p10; w1.y = p11;
            *(float2*)(Ps + qrow * AQ + ni * 8 + tq * 2)       = w0;
            *(float2*)(Ps + (qrow + 8) * AQ + ni * 8 + tq * 2) = w1;
        }
        rs0 += __shfl_xor_sync(0xffffffffu, rs0, 1);
        rs0 += __shfl_xor_sync(0xffffffffu, rs0, 2);
        rs1 += __shfl_xor_sync(0xffffffffu, rs1, 1);
        rs1 += __shfl_xor_sync(0xffffffffu, rs1, 2);
        l0 = l0 * c0f + rs0;
        l1 = l1 * c1f + rs1;

        #pragma unroll
        for (int ni = 0; ni < 8; ni++) {
            o[ni][0] *= c0f; o[ni][1] *= c0f;
            o[ni][2] *= c1f; o[ni][3] *= c1f;
        }
        __syncwarp();

        #pragma unroll
        for (int kk = 0; kk < 8; kk++) {
            const int k0 = kk * 8;
            uint32_t a[4];
            a[0] = f2tf(Ps[qrow * AQ + k0 + tq]);
            a[1] = f2tf(Ps[(qrow + 8) * AQ + k0 + tq]);
            a[2] = f2tf(Ps[qrow * AQ + k0 + tq + 4]);
            a[3] = f2tf(Ps[(qrow + 8) * AQ + k0 + tq + 4]);
            #pragma unroll
            for (int ni = 0; ni < 8; ni++) {
                uint32_t bb[2];
                bb[0] = f2tf(Vs[(k0 + tq) * AQ + ni * 8 + gid]);
                bb[1] = f2tf(Vs[(k0 + tq + 4) * AQ + ni * 8 + gid]);
                mma_tf32(o[ni], a, bb);
            }
        }
    }

    const float i0 = 1.f / l0, i1 = 1.f / l1;
    float* op0 = ctx + ((size_t)(b * SEQ) + grow0) * (NHEAD * HDIM) + h * HDIM;
    float* op1 = ctx + ((size_t)(b * SEQ) + grow1) * (NHEAD * HDIM) + h * HDIM;
    #pragma unroll
    for (int ni = 0; ni < 8; ni++) {
        float2 v0; v0.x = o[ni][0] * i0; v0.y = o[ni][1] * i0;
        float2 v1; v1.x = o[ni][2] * i1; v1.y = o[ni][3] * i1;
        *(float2*)(op0 + ni * 8 + tq * 2) = v0;
        *(float2*)(op1 + ni * 8 + tq * 2) = v1;
    }
}

// ---------------------------------------------------------------------------
// Host: tensormap encoding via runtime-resolved driver entry point
// ---------------------------------------------------------------------------
typedef CUresult (*PFN_encodeTiled)(
    CUtensorMap*, CUtensorMapDataType, cuuint32_t, void*,
    const cuuint64_t*, const cuuint64_t*, const cuuint32_t*, const cuuint32_t*,
    CUtensorMapInterleave, CUtensorMapSwizzle, CUtensorMapL2promotion,
    CUtensorMapFloatOOBfill);

static void encode2d(PFN_encodeTiled fn, CUtensorMap* tm,
                     const void* gptr, uint64_t inner, uint64_t outer)
{
    cuuint64_t dims[2]    = {inner, outer};
    cuuint64_t strides[1] = {inner * 4};
    cuuint32_t box[2]     = {32u, 128u};
    cuuint32_t es[2]      = {1u, 1u};
    fn(tm, CU_TENSOR_MAP_DATA_TYPE_FLOAT32, 2, (void*)gptr,
       dims, strides, box, es,
       CU_TENSOR_MAP_INTERLEAVE_NONE, CU_TENSOR_MAP_SWIZZLE_128B,
       CU_TENSOR_MAP_L2_PROMOTION_L2_128B, CU_TENSOR_MAP_FLOAT_OOB_FILL_NONE);
}

extern "C" void kernel_launch(void* const* d_in, const int* in_sizes, int n_in,
                              void* d_out, int out_size)
{
    const float* x     = (const float*)d_in[0];
    const float* ln_w  = (const float*)d_in[1];
    const float* ln_b  = (const float*)d_in[2];
    const float* wqkv  = (const float*)d_in[3];
    const float* bqkv  = (const float*)d_in[4];
    const float* wout  = (const float*)d_in[5];
    const float* bout  = (const float*)d_in[6];
    const float* fc1_w = (const float*)d_in[7];
    const float* fc1_b = (const float*)d_in[8];
    const float* fc2_w = (const float*)d_in[9];
    const float* fc2_b = (const float*)d_in[10];
    float* out = (float*)d_out;

    float *h, *qkv, *ctx, *attn, *ff;
    cudaGetSymbolAddress((void**)&h,    g_h);
    cudaGetSymbolAddress((void**)&qkv,  g_qkv);
    cudaGetSymbolAddress((void**)&ctx,  g_ctx);
    cudaGetSymbolAddress((void**)&attn, g_attn);
    cudaGetSymbolAddress((void**)&ff,   g_ff);

    void* fnp = nullptr;
    cudaDriverEntryPointQueryResult qres;
    cudaGetDriverEntryPoint("cuTensorMapEncodeTiled", &fnp,
                            cudaEnableDefault, &qres);
    PFN_encodeTiled enc = (PFN_encodeTiled)fnp;

    CUtensorMap tm_h, tm_wqkv, tm_ctx, tm_wout, tm_fc1, tm_ff, tm_fc2;
    encode2d(enc, &tm_h,    h,     D_MODEL, T_TOK);
    encode2d(enc, &tm_wqkv, wqkv,  D_MODEL, QKV_N);
    encode2d(enc, &tm_ctx,  ctx,   D_MODEL, T_TOK);
    encode2d(enc, &tm_wout, wout,  D_MODEL, D_MODEL);
    encode2d(enc, &tm_fc1,  fc1_w, D_MODEL, FF_N);
    encode2d(enc, &tm_ff,   ff,    FF_N,    T_TOK);
    encode2d(enc, &tm_fc2,  fc2_w, FF_N,    D_MODEL);

    cudaFuncSetAttribute(hmma_gemm<0>, cudaFuncAttributeMaxDynamicSharedMemorySize, GSMEM);
    cudaFuncSetAttribute(hmma_gemm<1>, cudaFuncAttributeMaxDynamicSharedMemorySize, GSMEM);
    cudaFuncSetAttribute(hmma_gemm<2>, cudaFuncAttributeMaxDynamicSharedMemorySize, GSMEM);
    cudaFuncSetAttribute(attn_mma_kernel, cudaFuncAttributeMaxDynamicSharedMemorySize, ASMEM);

    // 1. LayerNorm
    ln_kernel<<<T_TOK, 256>>>(x, ln_w, ln_b, h);

    // 2. QKV projection
    hmma_gemm<0><<<dim3(QKV_N / 128, T_TOK / 128), 128, GSMEM>>>(
        tm_h, tm_wqkv, bqkv, qkv, nullptr, nullptr, QKV_N, D_MODEL);

    // 3. RoPE
    rope_kernel<<<(T_TOK * 40 * 16 + 255) / 256, 256>>>(qkv);

    // 4. Attention (tf32 MMA flash, heavy tiles first)
    attn_mma_kernel<<<dim3(SEQ / 64, NHEAD, 2), 128, ASMEM>>>(qkv, ctx);

    // 5. Out projection
    hmma_gemm<0><<<dim3(D_MODEL / 128, T_TOK / 128), 128, GSMEM>>>(
        tm_ctx, tm_wout, bout, attn, nullptr, nullptr, D_MODEL, D_MODEL);

    // 6. FC1 + GELU
    hmma_gemm<1><<<dim3(FF_N / 128, T_TOK / 128), 128, GSMEM>>>(
        tm_h, tm_fc1, fc1_b, ff, nullptr, nullptr, FF_N, D_MODEL);

    // 7. FC2 + residuals (attn_out + x)
    hmma_gemm<2><<<dim3(D_MODEL / 128, T_TOK / 128), 128, GSMEM>>>(
        tm_ff, tm_fc2, fc2_b, out, attn, x, D_MODEL, FF_N);
}

// round 16
// speedup vs baseline: 1.6267x; 1.6267x over previous
#include <cuda_runtime.h>
#include <cuda.h>
#include <cuda_bf16.h>
#include <math.h>
#include <stdint.h>

// Problem constants
#define T_TOK   2048
#define D_MODEL 2048
#define QKV_N   3072
#define FF_N    8192
#define SEQ     1024
#define NHEAD   32
#define NKV     8
#define HDIM    64

// ---------------------------------------------------------------------------
// Scratch (allocation-free: device globals)
// ---------------------------------------------------------------------------
__device__ float g_h   [T_TOK * (size_t)D_MODEL];
__device__ float g_qkv [T_TOK * (size_t)QKV_N];
__device__ float g_ctx [T_TOK * (size_t)D_MODEL];
__device__ float g_attn[T_TOK * (size_t)D_MODEL];
__device__ float g_ff  [T_TOK * (size_t)FF_N];

// ---------------------------------------------------------------------------
// Device helpers
// ---------------------------------------------------------------------------
__device__ __forceinline__ uint32_t smem_u32(const void* p) {
    uint32_t a;
    asm("{ .reg .u64 t; cvta.to.shared.u64 t, %1; cvt.u32.u64 %0, t; }"
        : "=r"(a) : "l"(p));
    return a;
}
__device__ __forceinline__ void mbar_init(uint32_t addr, uint32_t cnt) {
    asm volatile("mbarrier.init.shared.b64 [%0], %1;" :: "r"(addr), "r"(cnt) : "memory");
}
__device__ __forceinline__ void mbar_expect(uint32_t addr, uint32_t bytes) {
    asm volatile("mbarrier.arrive.expect_tx.shared.b64 _, [%0], %1;"
                 :: "r"(addr), "r"(bytes) : "memory");
}
__device__ __forceinline__ void mbar_wait(uint32_t addr, int parity) {
    uint32_t done;
    asm volatile("{\n\t.reg .pred p;\n\t"
        "mbarrier.try_wait.parity.acquire.cta.shared::cta.b64 p, [%1], %2;\n\t"
        "selp.b32 %0, 1, 0, p;\n\t}"
        : "=r"(done) : "r"(addr), "r"((uint32_t)parity) : "memory");
    while (!done) {
        asm volatile("{\n\t.reg .pred p;\n\t"
            "mbarrier.try_wait.parity.acquire.cta.shared::cta.b64 p, [%1], %2, 0x989680;\n\t"
            "selp.b32 %0, 1, 0, p;\n\t}"
            : "=r"(done) : "r"(addr), "r"((uint32_t)parity) : "memory");
    }
}
__device__ __forceinline__ void tma2d(uint32_t smem, const CUtensorMap* tm,
                                      int cx, int cy, uint32_t mbar) {
    asm volatile(
        "cp.async.bulk.tensor.2d.shared::cta.global.tile.mbarrier::complete_tx::bytes "
        "[%0], [%1, {%2, %3}], [%4];"
        :: "r"(smem), "l"(tm), "r"(cx), "r"(cy), "r"(mbar) : "memory");
}
__device__ __forceinline__ uint32_t f2tf(float f) {
    uint32_t o;
    asm("cvt.rna.tf32.f32 %0, %1;" : "=r"(o) : "f"(f));
    return o;
}
__device__ __forceinline__ void mma_tf32(float* c, const uint32_t* a, const uint32_t* b) {
    asm volatile(
        "mma.sync.aligned.m16n8k8.row.col.f32.tf32.tf32.f32 "
        "{%0,%1,%2,%3}, {%4,%5,%6,%7}, {%8,%9}, {%0,%1,%2,%3};"
        : "+f"(c[0]), "+f"(c[1]), "+f"(c[2]), "+f"(c[3])
        : "r"(a[0]), "r"(a[1]), "r"(a[2]), "r"(a[3]), "r"(b[0]), "r"(b[1]));
}
// SW128 swizzle for 128B rows of fp32 (32 floats): 16B chunk ^= row&7
__device__ __forceinline__ int swidx(int row, int col) {
    return row * 32 + ((((col >> 2) ^ row) & 7) << 2) + (col & 3);
}
__device__ __forceinline__ float gelu_tanh(float v) {
    float v3 = v * v * v;
    return 0.5f * v * (1.f + tanhf(0.7978845608028654f * (v + 0.044715f * v3)));
}

// ---------------------------------------------------------------------------
// tf32 HMMA GEMM: C[M,N] = A[M,K] @ B[N,K]^T + bias  (exact R9 kernel)
// 128x128 CTA tile, BK=32, 4 warps (64x64 each), TMA double-buffered SW128.
// MODE 0: fp32 C    MODE 1: gelu fp32 C    MODE 2: fp32 C + R1 + R2
// ---------------------------------------------------------------------------
#define TILE_BYTES 16384
#define STAGE_TX   32768
#define GSMEM (1024 + 1024 + 4 * TILE_BYTES)

template<int MODE>
__global__ __launch_bounds__(128) void hmma_gemm(
    const __grid_constant__ CUtensorMap tmA,
    const __grid_constant__ CUtensorMap tmB,
    const float* __restrict__ bias, float* __restrict__ C,
    const float* __restrict__ R1, const float* __restrict__ R2,
    int N, int K)
{
    extern __shared__ char dsm[];
    const uint32_t raw  = smem_u32(dsm);
    const uint32_t base = (raw + 1023) & ~1023u;
    const uint32_t mb   = base;
    const uint32_t offA = base + 1024;
    const uint32_t offB = offA + 2 * TILE_BYTES;
    char* smbase = dsm + (base - raw);

    const int tid  = threadIdx.x;
    const int warp = tid >> 5, lane = tid & 31;
    const int gid  = lane >> 2, tq = lane & 3;
    const int wm   = (warp & 1) * 64, wn = (warp >> 1) * 64;
    const int tm   = blockIdx.y, tn = blockIdx.x;

    if (tid == 0) { mbar_init(mb, 1); mbar_init(mb + 8, 1); }
    __syncthreads();

    float acc[4][8][4];
    #pragma unroll
    for (int mi = 0; mi < 4; mi++)
        #pragma unroll
        for (int ni = 0; ni < 8; ni++)
            #pragma unroll
            for (int r = 0; r < 4; r++) acc[mi][ni][r] = 0.f;

    const int NI = K >> 5;
    if (tid == 0) {
        mbar_expect(mb, STAGE_TX);
        tma2d(offA, &tmA, 0, tm * 128, mb);
        tma2d(offB, &tmB, 0, tn * 128, mb);
    }
    int ph[2] = {0, 0};

    for (int i = 0; i < NI; i++) {
        const int s = i & 1;
        __syncthreads();
        if (i + 1 < NI && tid == 0) {
            const int s2 = (i + 1) & 1;
            const uint32_t m2 = mb + 8 * s2;
            mbar_expect(m2, STAGE_TX);
            tma2d(offA + s2 * TILE_BYTES, &tmA, (i + 1) * 32, tm * 128, m2);
            tma2d(offB + s2 * TILE_BYTES, &tmB, (i + 1) * 32, tn * 128, m2);
        }
        mbar_wait(mb + 8 * s, ph[s]); ph[s] ^= 1;

        const float* As = (const float*)(smbase + 1024 + s * TILE_BYTES);
        const float* Bs = (const float*)(smbase + 1024 + 2 * TILE_BYTES + s * TILE_BYTES);

        #pragma unroll
        for (int ks = 0; ks < 4; ks++) {
            const int k0 = ks * 8;
            uint32_t a[4][4], b[8][2];
            #pragma unroll
            for (int mi = 0; mi < 4; mi++) {
                const int r = wm + mi * 16 + gid;
                a[mi][0] = f2tf(As[swidx(r,     k0 + tq)]);
                a[mi][1] = f2tf(As[swidx(r + 8, k0 + tq)]);
                a[mi][2] = f2tf(As[swidx(r,     k0 + tq + 4)]);
                a[mi][3] = f2tf(As[swidx(r + 8, k0 + tq + 4)]);
            }
            #pragma unroll
            for (int ni = 0; ni < 8; ni++) {
                const int n = wn + ni * 8 + gid;
                b[ni][0] = f2tf(Bs[swidx(n, k0 + tq)]);
                b[ni][1] = f2tf(Bs[swidx(n, k0 + tq + 4)]);
            }
            #pragma unroll
            for (int mi = 0; mi < 4; mi++)
                #pragma unroll
                for (int ni = 0; ni < 8; ni++)
                    mma_tf32(acc[mi][ni], a[mi], b[ni]);
        }
    }

    #pragma unroll
    for (int mi = 0; mi < 4; mi++) {
        #pragma unroll
        for (int half = 0; half < 2; half++) {
            const int m = tm * 128 + wm + mi * 16 + gid + half * 8;
            #pragma unroll
            for (int ni = 0; ni < 8; ni++) {
                const int col = tn * 128 + wn + ni * 8 + tq * 2;
                float v0 = acc[mi][ni][half * 2 + 0] + __ldg(&bias[col]);
                float v1 = acc[mi][ni][half * 2 + 1] + __ldg(&bias[col + 1]);
                if (MODE == 1) { v0 = gelu_tanh(v0); v1 = gelu_tanh(v1); }
                const size_t idx = (size_t)m * N + col;
                if (MODE == 2) {
                    v0 += R1[idx]     + R2[idx];
                    v1 += R1[idx + 1] + R2[idx + 1];
                }
                float2 o; o.x = v0; o.y = v1;
                *(float2*)(C + idx) = o;
            }
        }
    }
}

// ---------------------------------------------------------------------------
// LayerNorm
// ---------------------------------------------------------------------------
__global__ __launch_bounds__(256) void ln_kernel(
    const float* __restrict__ x, const float* __restrict__ w,
    const float* __restrict__ b, float* __restrict__ out)
{
    const int t = blockIdx.x;
    const float* xr = x + (size_t)t * D_MODEL;
    float sum = 0.f, sq = 0.f;
    for (int i = threadIdx.x; i < D_MODEL; i += 256) {
        float v = xr[i]; sum += v; sq += v * v;
    }
    #pragma unroll
    for (int o = 16; o; o >>= 1) {
        sum += __shfl_xor_sync(0xffffffffu, sum, o);
        sq  += __shfl_xor_sync(0xffffffffu, sq,  o);
    }
    __shared__ float s1[8], s2[8];
    __shared__ float mu_s, rs_s;
    const int wid = threadIdx.x >> 5, lane = threadIdx.x & 31;
    if (!lane) { s1[wid] = sum; s2[wid] = sq; }
    __syncthreads();
    if (threadIdx.x == 0) {
        float a = 0.f, c = 0.f;
        #pragma unroll
        for (int i = 0; i < 8; i++) { a += s1[i]; c += s2[i]; }
        float mu = a / D_MODEL;
        float var = c / D_MODEL - mu * mu;
        mu_s = mu; rs_s = rsqrtf(var + 1e-5f);
    }
    __syncthreads();
    const float mu = mu_s, rs = rs_s;
    float* orow = out + (size_t)t * D_MODEL;
    for (int i = threadIdx.x; i < D_MODEL; i += 256)
        orow[i] = (xr[i] - mu) * rs * w[i] + b[i];
}

// ---------------------------------------------------------------------------
// RoPE (in place on g_qkv)
// ---------------------------------------------------------------------------
__global__ void rope_kernel(float* __restrict__ qkv)
{
    const int idx = blockIdx.x * blockDim.x + threadIdx.x;
    if (idx >= T_TOK * 40 * 16) return;
    const int pair = idx & 15;
    const int head = (idx >> 4) % 40;
    const int t    = idx / (16 * 40);
    const int pos  = t & (SEQ - 1);
    const size_t row = (size_t)t * QKV_N;
    const int off = (head < NHEAD) ? head * HDIM
                                   : NHEAD * HDIM + (head - NHEAD) * HDIM;
    const float u1 = qkv[row + off + pair];
    const float u2 = qkv[row + off + 16 + pair];
    const float inv = powf(10000.f, -(float)(2 * pair) / 32.f);
    float s, c;
    sincosf((float)pos * inv, &s, &c);
    qkv[row + off + pair]      = u1 * c - u2 * s;
    qkv[row + off + 16 + pair] = u1 * s + u2 * c;
}

// ---------------------------------------------------------------------------
// tf32 MMA causal flash attention (R9 fragment math).
// Changes vs R9: Q fragments hoisted to registers (loop-invariant), and the
// P scratch overlays the dead Q SMEM region -> 51KB smem, 4 CTAs/SM.
// ---------------------------------------------------------------------------
#define AQ 68
#define ASMEM (3 * 64 * AQ * 4)

__global__ __launch_bounds__(128) void attn_mma_kernel(
    const float* __restrict__ qkv, float* __restrict__ ctx)
{
    extern __shared__ float smf[];
    float* Qs = smf;                    // prologue only
    float* Ks = Qs + 64 * AQ;
    float* Vs = Ks + 64 * AQ;
    float* Ps = Qs;                     // overlay: Q dead after hoist

    const int qt = blockIdx.x, h = blockIdx.y, b = blockIdx.z;
    const int tid  = threadIdx.x;
    const int warp = tid >> 5, lane = tid & 31;
    const int gid  = lane >> 2, tq = lane & 3;
    const int kvh  = h >> 2;
    const float* base = qkv + (size_t)b * SEQ * QKV_N;

    // Cooperative Q tile fill
    {
        const int r = tid >> 1, half = tid & 1;
        const float* src = base + (size_t)(qt * 64 + r) * QKV_N + h * HDIM + half * 32;
        float* dst = Qs + r * AQ + half * 32;
        #pragma unroll
        for (int i = 0; i < 8; i++)
            *(float4*)(dst + i * 4) = *(const float4*)(src + i * 4);
    }
    __syncthreads();

    const int qrow  = warp * 16 + gid;
    const int grow0 = qt * 64 + qrow;
    const int grow1 = grow0 + 8;
    const float scale = 0.125f;

    // Hoist Q fragments (loop-invariant across kt)
    uint32_t qa[8][4];
    #pragma unroll
    for (int kk = 0; kk < 8; kk++) {
        const int k0 = kk * 8;
        qa[kk][0] = f2tf(Qs[qrow * AQ + k0 + tq]);
        qa[kk][1] = f2tf(Qs[(qrow + 8) * AQ + k0 + tq]);
        qa[kk][2] = f2tf(Qs[qrow * AQ + k0 + tq + 4]);
        qa[kk][3] = f2tf(Qs[(qrow + 8) * AQ + k0 + tq + 4]);
    }

    float m0 = -1e30f, m1 = -1e30f, l0 = 0.f, l1 = 0.f;
    float o[8][4];
    #pragma unroll
    for (int ni = 0; ni < 8; ni++)
        #pragma unroll
        for (int r = 0; r < 4; r++) o[ni][r] = 0.f;

    for (int kt = 0; kt <= qt; ++kt) {
        __syncthreads();                 // prior tile reads (and Q hoist) done
        {
            const int r = tid >> 1, half = tid & 1;
            const float* ks = base + (size_t)(kt * 64 + r) * QKV_N
                              + NHEAD * HDIM + kvh * HDIM + half * 32;
            const float* vs = ks + NKV * HDIM;
            float* kd = Ks + r * AQ + half * 32;
            float* vd = Vs + r * AQ + half * 32;
            #pragma unroll
            for (int i = 0; i < 8; i++) {
                *(float4*)(kd + i * 4) = *(const float4*)(ks + i * 4);
                *(float4*)(vd + i * 4) = *(const float4*)(vs + i * 4);
            }
        }
        __syncthreads();

        // S = Q @ K^T
        float s[8][4];
        #pragma unroll
        for (int ni = 0; ni < 8; ni++)
            #pragma unroll
            for (int r = 0; r < 4; r++) s[ni][r] = 0.f;

        #pragma unroll
        for (int kk = 0; kk < 8; kk++) {
            const int k0 = kk * 8;
            #pragma unroll
            for (int ni = 0; ni < 8; ni++) {
                uint32_t bb[2];
                bb[0] = f2tf(Ks[(ni * 8 + gid) * AQ + k0 + tq]);
                bb[1] = f2tf(Ks[(ni * 8 + gid) * AQ + k0 + tq + 4]);
                mma_tf32(s[ni], qa[kk], bb);
            }
        }

        #pragma unroll
        for (int ni = 0; ni < 8; ni++) {
            #pragma unroll
            for (int r = 0; r < 4; r++) s[ni][r] *= scale;
        }
        if (kt == qt) {
            #pragma unroll
            for (int ni = 0; ni < 8; ni++) {
                const int c0 = kt * 64 + ni * 8 + tq * 2;
                if (c0     > grow0) s[ni][0] = -1e30f;
                if (c0 + 1 > grow0) s[ni][1] = -1e30f;
                if (c0     > grow1) s[ni][2] = -1e30f;
                if (c0 + 1 > grow1) s[ni][3] = -1e30f;
            }
        }

        float r0 = -1e30f, r1 = -1e30f;
        #pragma unroll
        for (int ni = 0; ni < 8; ni++) {
            r0 = fmaxf(r0, fmaxf(s[ni][0], s[ni][1]));
            r1 = fmaxf(r1, fmaxf(s[ni][2], s[ni][3]));
        }
        r0 = fmaxf(r0, __shfl_xor_sync(0xffffffffu, r0, 1));
        r0 = fmaxf(r0, __shfl_xor_sync(0xffffffffu, r0, 2));
        r1 = fmaxf(r1, __shfl_xor_sync(0xffffffffu, r1, 1));
        r1 = fmaxf(r1, __shfl_xor_sync(0xffffffffu, r1, 2));

        const float mn0 = fmaxf(m0, r0), mn1 = fmaxf(m1, r1);
        const float c0f = __expf(m0 - mn0), c1f = __expf(m1 - mn1);
        m0 = mn0; m1 = mn1;

        float rs0 = 0.f, rs1 = 0.f;
        #pragma unroll
        for (int ni = 0; ni < 8; ni++) {
            const float p00 = __expf(s[ni][0] - mn0);
            const float p01 = __expf(s[ni][1] - mn0);
            const float p10 = __expf(s[ni][2] - mn1);
            const float p11 = __expf(s[ni][3] - mn1);
            rs0 += p00 + p01; rs1 += p10 + p11;
            float2 w0; w0.x = p00; w0.y = p01;
            float2 w1; w1.x = p10; w1.y = p11;
            *(float2*)(Ps + qrow * AQ + ni * 8 + tq * 2)       = w0;
            *(float2*)(Ps + (qrow + 8) * AQ + ni * 8 + tq * 2) = w1;
        }
        rs0 += __shfl_xor_sync(0xffffffffu, rs0, 1);
        rs0 += __shfl_xor_sync(0xffffffffu, rs0, 2);
        rs1 += __shfl_xor_sync(0xffffffffu, rs1, 1);
        rs1 += __shfl_xor_sync(0xffffffffu, rs1, 2);
        l0 = l0 * c0f + rs0;
        l1 = l1 * c1f + rs1;

        #pragma unroll
        for (int ni = 0; ni < 8; ni++) {
            o[ni][0] *= c0f; o[ni][1] *= c0f;
            o[ni][2] *= c1f; o[ni][3] *= c1f;
        }
        __syncwarp();                    // Ps rows are warp-local

        // O += P @ V
        #pragma unroll
        for (int kk = 0; kk < 8; kk++) {
            const int k0 = kk * 8;
            uint32_t a[4];
            a[0] = f2tf(Ps[qrow * AQ + k0 + tq]);
            a[1] = f2tf(Ps[(qrow + 8) * AQ + k0 + tq]);
            a[2] = f2tf(Ps[qrow * AQ + k0 + tq + 4]);
            a[3] = f2tf(Ps[(qrow + 8) * AQ + k0 + tq + 4]);
            #pragma unroll
            for (int ni = 0; ni < 8; ni++) {
                uint32_t bb[2];
                bb[0] = f2tf(Vs[(k0 + tq) * AQ + ni * 8 + gid]);
                bb[1] = f2tf(Vs[(k0 + tq + 4) * AQ + ni * 8 + gid]);
                mma_tf32(o[ni], a, bb);
            }
        }
    }

    const float i0 = 1.f / l0, i1 = 1.f / l1;
    float* op0 = ctx + ((size_t)(b * SEQ) + grow0) * (NHEAD * HDIM) + h * HDIM;
    float* op1 = ctx + ((size_t)(b * SEQ) + grow1) * (NHEAD * HDIM) + h * HDIM;
    #pragma unroll
    for (int ni = 0; ni < 8; ni++) {
        float2 v0; v0.x = o[ni][0] * i0; v0.y = o[ni][1] * i0;
        float2 v1; v1.x = o[ni][2] * i1; v1.y = o[ni][3] * i1;
        *(float2*)(op0 + ni * 8 + tq * 2) = v0;
        *(float2*)(op1 + ni * 8 + tq * 2) = v1;
    }
}

// ---------------------------------------------------------------------------
// Host: tensormap encoding via runtime-resolved driver entry point
// ---------------------------------------------------------------------------
typedef CUresult (*PFN_encodeTiled)(
    CUtensorMap*, CUtensorMapDataType, cuuint32_t, void*,
    const cuuint64_t*, const cuuint64_t*, const cuuint32_t*, const cuuint32_t*,
    CUtensorMapInterleave, CUtensorMapSwizzle, CUtensorMapL2promotion,
    CUtensorMapFloatOOBfill);

static void encode2d(PFN_encodeTiled fn, CUtensorMap* tm,
                     const void* gptr, uint64_t inner, uint64_t outer)
{
    cuuint64_t dims[2]    = {inner, outer};
    cuuint64_t strides[1] = {inner * 4};
    cuuint32_t box[2]     = {32u, 128u};
    cuuint32_t es[2]      = {1u, 1u};
    fn(tm, CU_TENSOR_MAP_DATA_TYPE_FLOAT32, 2, (void*)gptr,
       dims, strides, box, es,
       CU_TENSOR_MAP_INTERLEAVE_NONE, CU_TENSOR_MAP_SWIZZLE_128B,
       CU_TENSOR_MAP_L2_PROMOTION_L2_128B, CU_TENSOR_MAP_FLOAT_OOB_FILL_NONE);
}

extern "C" void kernel_launch(void* const* d_in, const int* in_sizes, int n_in,
                              void* d_out, int out_size)
{
    const float* x     = (const float*)d_in[0];
    const float* ln_w  = (const float*)d_in[1];
    const float* ln_b  = (const float*)d_in[2];
    const float* wqkv  = (const float*)d_in[3];
    const float* bqkv  = (const float*)d_in[4];
    const float* wout  = (const float*)d_in[5];
    const float* bout  = (const float*)d_in[6];
    const float* fc1_w = (const float*)d_in[7];
    const float* fc1_b = (const float*)d_in[8];
    const float* fc2_w = (const float*)d_in[9];
    const float* fc2_b = (const float*)d_in[10];
    float* out = (float*)d_out;

    float *h, *qkv, *ctx, *attn, *ff;
    cudaGetSymbolAddress((void**)&h,    g_h);
    cudaGetSymbolAddress((void**)&qkv,  g_qkv);
    cudaGetSymbolAddress((void**)&ctx,  g_ctx);
    cudaGetSymbolAddress((void**)&attn, g_attn);
    cudaGetSymbolAddress((void**)&ff,   g_ff);

    void* fnp = nullptr;
    cudaDriverEntryPointQueryResult qres;
    cudaGetDriverEntryPoint("cuTensorMapEncodeTiled", &fnp,
                            cudaEnableDefault, &qres);
    PFN_encodeTiled enc = (PFN_encodeTiled)fnp;

    CUtensorMap tm_h, tm_wqkv, tm_ctx, tm_wout, tm_fc1, tm_ff, tm_fc2;
    encode2d(enc, &tm_h,    h,     D_MODEL, T_TOK);
    encode2d(enc, &tm_wqkv, wqkv,  D_MODEL, QKV_N);
    encode2d(enc, &tm_ctx,  ctx,   D_MODEL, T_TOK);
    encode2d(enc, &tm_wout, wout,  D_MODEL, D_MODEL);
    encode2d(enc, &tm_fc1,  fc1_w, D_MODEL, FF_N);
    encode2d(enc, &tm_ff,   ff,    FF_N,    T_TOK);
    encode2d(enc, &tm_fc2,  fc2_w, FF_N,    D_MODEL);

    cudaFuncSetAttribute(hmma_gemm<0>, cudaFuncAttributeMaxDynamicSharedMemorySize, GSMEM);
    cudaFuncSetAttribute(hmma_gemm<1>, cudaFuncAttributeMaxDynamicSharedMemorySize, GSMEM);
    cudaFuncSetAttribute(hmma_gemm<2>, cudaFuncAttributeMaxDynamicSharedMemorySize, GSMEM);
    cudaFuncSetAttribute(attn_mma_kernel, cudaFuncAttributeMaxDynamicSharedMemorySize, ASMEM);

    // 1. LayerNorm
    ln_kernel<<<T_TOK, 256>>>(x, ln_w, ln_b, h);

    // 2. QKV projection
    hmma_gemm<0><<<dim3(QKV_N / 128, T_TOK / 128), 128, GSMEM>>>(
        tm_h, tm_wqkv, bqkv, qkv, nullptr, nullptr, QKV_N, D_MODEL);

    // 3. RoPE
    rope_kernel<<<(T_TOK * 40 * 16 + 255) / 256, 256>>>(qkv);

    // 4. Attention (tf32 MMA flash, Q frags hoisted, P overlays Q smem)
    attn_mma_kernel<<<dim3(SEQ / 64, NHEAD, 2), 128, ASMEM>>>(qkv, ctx);

    // 5. Out projection
    hmma_gemm<0><<<dim3(D_MODEL / 128, T_TOK / 128), 128, GSMEM>>>(
        tm_ctx, tm_wout, bout, attn, nullptr, nullptr, D_MODEL, D_MODEL);

    // 6. FC1 + GELU
    hmma_gemm<1><<<dim3(FF_N / 128, T_TOK / 128), 128, GSMEM>>>(
        tm_h, tm_fc1, fc1_b, ff, nullptr, nullptr, FF_N, D_MODEL);

    // 7. FC2 + residuals (attn_out + x)
    hmma_gemm<2><<<dim3(D_MODEL / 128, T_TOK / 128), 128, GSMEM>>>(
        tm_ff, tm_fc2, fc2_b, out, attn, x, D_MODEL, FF_N);
}

// round 17
// speedup vs baseline: 1.6361x; 1.0058x over previous
#include <cuda_runtime.h>
#include <cuda.h>
#include <cuda_bf16.h>
#include <math.h>
#include <stdint.h>

// Problem constants
#define T_TOK   2048
#define D_MODEL 2048
#define QKV_N   3072
#define FF_N    8192
#define SEQ     1024
#define NHEAD   32
#define NKV     8
#define HDIM    64

// ---------------------------------------------------------------------------
// Scratch (allocation-free: device globals)
// ---------------------------------------------------------------------------
__device__ float g_h   [T_TOK * (size_t)D_MODEL];
__device__ float g_qkv [T_TOK * (size_t)QKV_N];
__device__ float g_ctx [T_TOK * (size_t)D_MODEL];
__device__ float g_attn[T_TOK * (size_t)D_MODEL];
__device__ float g_ff  [T_TOK * (size_t)FF_N];

// ---------------------------------------------------------------------------
// Device helpers
// ---------------------------------------------------------------------------
__device__ __forceinline__ uint32_t smem_u32(const void* p) {
    uint32_t a;
    asm("{ .reg .u64 t; cvta.to.shared.u64 t, %1; cvt.u32.u64 %0, t; }"
        : "=r"(a) : "l"(p));
    return a;
}
__device__ __forceinline__ void mbar_init(uint32_t addr, uint32_t cnt) {
    asm volatile("mbarrier.init.shared.b64 [%0], %1;" :: "r"(addr), "r"(cnt) : "memory");
}
__device__ __forceinline__ void mbar_expect(uint32_t addr, uint32_t bytes) {
    asm volatile("mbarrier.arrive.expect_tx.shared.b64 _, [%0], %1;"
                 :: "r"(addr), "r"(bytes) : "memory");
}
__device__ __forceinline__ void mbar_wait(uint32_t addr, int parity) {
    uint32_t done;
    asm volatile("{\n\t.reg .pred p;\n\t"
        "mbarrier.try_wait.parity.acquire.cta.shared::cta.b64 p, [%1], %2;\n\t"
        "selp.b32 %0, 1, 0, p;\n\t}"
        : "=r"(done) : "r"(addr), "r"((uint32_t)parity) : "memory");
    while (!done) {
        asm volatile("{\n\t.reg .pred p;\n\t"
            "mbarrier.try_wait.parity.acquire.cta.shared::cta.b64 p, [%1], %2, 0x989680;\n\t"
            "selp.b32 %0, 1, 0, p;\n\t}"
            : "=r"(done) : "r"(addr), "r"((uint32_t)parity) : "memory");
    }
}
__device__ __forceinline__ void tma2d(uint32_t smem, const CUtensorMap* tm,
                                      int cx, int cy, uint32_t mbar) {
    asm volatile(
        "cp.async.bulk.tensor.2d.shared::cta.global.tile.mbarrier::complete_tx::bytes "
        "[%0], [%1, {%2, %3}], [%4];"
        :: "r"(smem), "l"(tm), "r"(cx), "r"(cy), "r"(mbar) : "memory");
}
__device__ __forceinline__ uint32_t f2tf(float f) {
    uint32_t o;
    asm("cvt.rna.tf32.f32 %0, %1;" : "=r"(o) : "f"(f));
    return o;
}
__device__ __forceinline__ void mma_tf32(float* c, const uint32_t* a, const uint32_t* b) {
    asm volatile(
        "mma.sync.aligned.m16n8k8.row.col.f32.tf32.tf32.f32 "
        "{%0,%1,%2,%3}, {%4,%5,%6,%7}, {%8,%9}, {%0,%1,%2,%3};"
        : "+f"(c[0]), "+f"(c[1]), "+f"(c[2]), "+f"(c[3])
        : "r"(a[0]), "r"(a[1]), "r"(a[2]), "r"(a[3]), "r"(b[0]), "r"(b[1]));
}
// SW128 swizzle for 128B rows of fp32 (32 floats): 16B chunk ^= row&7
__device__ __forceinline__ int swidx(int row, int col) {
    return row * 32 + ((((col >> 2) ^ row) & 7) << 2) + (col & 3);
}
__device__ __forceinline__ float gelu_tanh(float v) {
    float v3 = v * v * v;
    return 0.5f * v * (1.f + tanhf(0.7978845608028654f * (v + 0.044715f * v3)));
}

// ---------------------------------------------------------------------------
// tf32 HMMA GEMM: C[M,N] = A[M,K] @ B[N,K]^T + bias  (exact R16 kernel)
// 128x128 CTA tile, BK=32, 4 warps (64x64 each), TMA double-buffered SW128.
// MODE 0: fp32 C    MODE 1: gelu fp32 C    MODE 2: fp32 C + R1 + R2
// ---------------------------------------------------------------------------
#define TILE_BYTES 16384
#define STAGE_TX   32768
#define GSMEM (1024 + 1024 + 4 * TILE_BYTES)

template<int MODE>
__global__ __launch_bounds__(128) void hmma_gemm(
    const __grid_constant__ CUtensorMap tmA,
    const __grid_constant__ CUtensorMap tmB,
    const float* __restrict__ bias, float* __restrict__ C,
    const float* __restrict__ R1, const float* __restrict__ R2,
    int N, int K)
{
    extern __shared__ char dsm[];
    const uint32_t raw  = smem_u32(dsm);
    const uint32_t base = (raw + 1023) & ~1023u;
    const uint32_t mb   = base;
    const uint32_t offA = base + 1024;
    const uint32_t offB = offA + 2 * TILE_BYTES;
    char* smbase = dsm + (base - raw);

    const int tid  = threadIdx.x;
    const int warp = tid >> 5, lane = tid & 31;
    const int gid  = lane >> 2, tq = lane & 3;
    const int wm   = (warp & 1) * 64, wn = (warp >> 1) * 64;
    const int tm   = blockIdx.y, tn = blockIdx.x;

    if (tid == 0) { mbar_init(mb, 1); mbar_init(mb + 8, 1); }
    __syncthreads();

    float acc[4][8][4];
    #pragma unroll
    for (int mi = 0; mi < 4; mi++)
        #pragma unroll
        for (int ni = 0; ni < 8; ni++)
            #pragma unroll
            for (int r = 0; r < 4; r++) acc[mi][ni][r] = 0.f;

    const int NI = K >> 5;
    if (tid == 0) {
        mbar_expect(mb, STAGE_TX);
        tma2d(offA, &tmA, 0, tm * 128, mb);
        tma2d(offB, &tmB, 0, tn * 128, mb);
    }
    int ph[2] = {0, 0};

    for (int i = 0; i < NI; i++) {
        const int s = i & 1;
        __syncthreads();
        if (i + 1 < NI && tid == 0) {
            const int s2 = (i + 1) & 1;
            const uint32_t m2 = mb + 8 * s2;
            mbar_expect(m2, STAGE_TX);
            tma2d(offA + s2 * TILE_BYTES, &tmA, (i + 1) * 32, tm * 128, m2);
            tma2d(offB + s2 * TILE_BYTES, &tmB, (i + 1) * 32, tn * 128, m2);
        }
        mbar_wait(mb + 8 * s, ph[s]); ph[s] ^= 1;

        const float* As = (const float*)(smbase + 1024 + s * TILE_BYTES);
        const float* Bs = (const float*)(smbase + 1024 + 2 * TILE_BYTES + s * TILE_BYTES);

        #pragma unroll
        for (int ks = 0; ks < 4; ks++) {
            const int k0 = ks * 8;
            uint32_t a[4][4], b[8][2];
            #pragma unroll
            for (int mi = 0; mi < 4; mi++) {
                const int r = wm + mi * 16 + gid;
                a[mi][0] = f2tf(As[swidx(r,     k0 + tq)]);
                a[mi][1] = f2tf(As[swidx(r + 8, k0 + tq)]);
                a[mi][2] = f2tf(As[swidx(r,     k0 + tq + 4)]);
                a[mi][3] = f2tf(As[swidx(r + 8, k0 + tq + 4)]);
            }
            #pragma unroll
            for (int ni = 0; ni < 8; ni++) {
                const int n = wn + ni * 8 + gid;
                b[ni][0] = f2tf(Bs[swidx(n, k0 + tq)]);
                b[ni][1] = f2tf(Bs[swidx(n, k0 + tq + 4)]);
            }
            #pragma unroll
            for (int mi = 0; mi < 4; mi++)
                #pragma unroll
                for (int ni = 0; ni < 8; ni++)
                    mma_tf32(acc[mi][ni], a[mi], b[ni]);
        }
    }

    #pragma unroll
    for (int mi = 0; mi < 4; mi++) {
        #pragma unroll
        for (int half = 0; half < 2; half++) {
            const int m = tm * 128 + wm + mi * 16 + gid + half * 8;
            #pragma unroll
            for (int ni = 0; ni < 8; ni++) {
                const int col = tn * 128 + wn + ni * 8 + tq * 2;
                float v0 = acc[mi][ni][half * 2 + 0] + __ldg(&bias[col]);
                float v1 = acc[mi][ni][half * 2 + 1] + __ldg(&bias[col + 1]);
                if (MODE == 1) { v0 = gelu_tanh(v0); v1 = gelu_tanh(v1); }
                const size_t idx = (size_t)m * N + col;
                if (MODE == 2) {
                    v0 += R1[idx]     + R2[idx];
                    v1 += R1[idx + 1] + R2[idx + 1];
                }
                float2 o; o.x = v0; o.y = v1;
                *(float2*)(C + idx) = o;
            }
        }
    }
}

// ---------------------------------------------------------------------------
// LayerNorm
// ---------------------------------------------------------------------------
__global__ __launch_bounds__(256) void ln_kernel(
    const float* __restrict__ x, const float* __restrict__ w,
    const float* __restrict__ b, float* __restrict__ out)
{
    const int t = blockIdx.x;
    const float* xr = x + (size_t)t * D_MODEL;
    float sum = 0.f, sq = 0.f;
    for (int i = threadIdx.x; i < D_MODEL; i += 256) {
        float v = xr[i]; sum += v; sq += v * v;
    }
    #pragma unroll
    for (int o = 16; o; o >>= 1) {
        sum += __shfl_xor_sync(0xffffffffu, sum, o);
        sq  += __shfl_xor_sync(0xffffffffu, sq,  o);
    }
    __shared__ float s1[8], s2[8];
    __shared__ float mu_s, rs_s;
    const int wid = threadIdx.x >> 5, lane = threadIdx.x & 31;
    if (!lane) { s1[wid] = sum; s2[wid] = sq; }
    __syncthreads();
    if (threadIdx.x == 0) {
        float a = 0.f, c = 0.f;
        #pragma unroll
        for (int i = 0; i < 8; i++) { a += s1[i]; c += s2[i]; }
        float mu = a / D_MODEL;
        float var = c / D_MODEL - mu * mu;
        mu_s = mu; rs_s = rsqrtf(var + 1e-5f);
    }
    __syncthreads();
    const float mu = mu_s, rs = rs_s;
    float* orow = out + (size_t)t * D_MODEL;
    for (int i = threadIdx.x; i < D_MODEL; i += 256)
        orow[i] = (xr[i] - mu) * rs * w[i] + b[i];
}

// ---------------------------------------------------------------------------
// RoPE (in place on g_qkv)
// ---------------------------------------------------------------------------
__global__ void rope_kernel(float* __restrict__ qkv)
{
    const int idx = blockIdx.x * blockDim.x + threadIdx.x;
    if (idx >= T_TOK * 40 * 16) return;
    const int pair = idx & 15;
    const int head = (idx >> 4) % 40;
    const int t    = idx / (16 * 40);
    const int pos  = t & (SEQ - 1);
    const size_t row = (size_t)t * QKV_N;
    const int off = (head < NHEAD) ? head * HDIM
                                   : NHEAD * HDIM + (head - NHEAD) * HDIM;
    const float u1 = qkv[row + off + pair];
    const float u2 = qkv[row + off + 16 + pair];
    const float inv = powf(10000.f, -(float)(2 * pair) / 32.f);
    float s, c;
    sincosf((float)pos * inv, &s, &c);
    qkv[row + off + pair]      = u1 * c - u2 * s;
    qkv[row + off + 16 + pair] = u1 * s + u2 * c;
}

// ---------------------------------------------------------------------------
// tf32 MMA causal flash attention (exact R16 kernel: Q frags hoisted,
// P overlays dead Q SMEM).
// ---------------------------------------------------------------------------
#define AQ 68
#define ASMEM (3 * 64 * AQ * 4)

__global__ __launch_bounds__(128) void attn_mma_kernel(
    const float* __restrict__ qkv, float* __restrict__ ctx)
{
    extern __shared__ float smf[];
    float* Qs = smf;                    // prologue only
    float* Ks = Qs + 64 * AQ;
    float* Vs = Ks + 64 * AQ;
    float* Ps = Qs;                     // overlay: Q dead after hoist

    const int qt = blockIdx.x, h = blockIdx.y, b = blockIdx.z;
    const int tid  = threadIdx.x;
    const int warp = tid >> 5, lane = tid & 31;
    const int gid  = lane >> 2, tq = lane & 3;
    const int kvh  = h >> 2;
    const float* base = qkv + (size_t)b * SEQ * QKV_N;

    // Cooperative Q tile fill
    {
        const int r = tid >> 1, half = tid & 1;
        const float* src = base + (size_t)(qt * 64 + r) * QKV_N + h * HDIM + half * 32;
        float* dst = Qs + r * AQ + half * 32;
        #pragma unroll
        for (int i = 0; i < 8; i++)
            *(float4*)(dst + i * 4) = *(const float4*)(src + i * 4);
    }
    __syncthreads();

    const int qrow  = warp * 16 + gid;
    const int grow0 = qt * 64 + qrow;
    const int grow1 = grow0 + 8;
    const float scale = 0.125f;

    // Hoist Q fragments (loop-invariant across kt)
    uint32_t qa[8][4];
    #pragma unroll
    for (int kk = 0; kk < 8; kk++) {
        const int k0 = kk * 8;
        qa[kk][0] = f2tf(Qs[qrow * AQ + k0 + tq]);
        qa[kk][1] = f2tf(Qs[(qrow + 8) * AQ + k0 + tq]);
        qa[kk][2] = f2tf(Qs[qrow * AQ + k0 + tq + 4]);
        qa[kk][3] = f2tf(Qs[(qrow + 8) * AQ + k0 + tq + 4]);
    }

    float m0 = -1e30f, m1 = -1e30f, l0 = 0.f, l1 = 0.f;
    float o[8][4];
    #pragma unroll
    for (int ni = 0; ni < 8; ni++)
        #pragma unroll
        for (int r = 0; r < 4; r++) o[ni][r] = 0.f;

    for (int kt = 0; kt <= qt; ++kt) {
        __syncthreads();                 // prior tile reads (and Q hoist) done
        {
            const int r = tid >> 1, half = tid & 1;
            const float* ks = base + (size_t)(kt * 64 + r) * QKV_N
                              + NHEAD * HDIM + kvh * HDIM + half * 32;
            const float* vs = ks + NKV * HDIM;
            float* kd = Ks + r * AQ + half * 32;
            float* vd = Vs + r * AQ + half * 32;
            #pragma unroll
            for (int i = 0; i < 8; i++) {
                *(float4*)(kd + i * 4) = *(const float4*)(ks + i * 4);
                *(float4*)(vd + i * 4) = *(const float4*)(vs + i * 4);
            }
        }
        __syncthreads();

        // S = Q @ K^T
        float s[8][4];
        #pragma unroll
        for (int ni = 0; ni < 8; ni++)
            #pragma unroll
            for (int r = 0; r < 4; r++) s[ni][r] = 0.f;

        #pragma unroll
        for (int kk = 0; kk < 8; kk++) {
            const int k0 = kk * 8;
            #pragma unroll
            for (int ni = 0; ni < 8; ni++) {
                uint32_t bb[2];
                bb[0] = f2tf(Ks[(ni * 8 + gid) * AQ + k0 + tq]);
                bb[1] = f2tf(Ks[(ni * 8 + gid) * AQ + k0 + tq + 4]);
                mma_tf32(s[ni], qa[kk], bb);
            }
        }

        #pragma unroll
        for (int ni = 0; ni < 8; ni++) {
            #pragma unroll
            for (int r = 0; r < 4; r++) s[ni][r] *= scale;
        }
        if (kt == qt) {
            #pragma unroll
            for (int ni = 0; ni < 8; ni++) {
                const int c0 = kt * 64 + ni * 8 + tq * 2;
                if (c0     > grow0) s[ni][0] = -1e30f;
                if (c0 + 1 > grow0) s[ni][1] = -1e30f;
                if (c0     > grow1) s[ni][2] = -1e30f;
                if (c0 + 1 > grow1) s[ni][3] = -1e30f;
            }
        }

        float r0 = -1e30f, r1 = -1e30f;
        #pragma unroll
        for (int ni = 0; ni < 8; ni++) {
            r0 = fmaxf(r0, fmaxf(s[ni][0], s[ni][1]));
            r1 = fmaxf(r1, fmaxf(s[ni][2], s[ni][3]));
        }
        r0 = fmaxf(r0, __shfl_xor_sync(0xffffffffu, r0, 1));
        r0 = fmaxf(r0, __shfl_xor_sync(0xffffffffu, r0, 2));
        r1 = fmaxf(r1, __shfl_xor_sync(0xffffffffu, r1, 1));
        r1 = fmaxf(r1, __shfl_xor_sync(0xffffffffu, r1, 2));

        const float mn0 = fmaxf(m0, r0), mn1 = fmaxf(m1, r1);
        const float c0f = __expf(m0 - mn0), c1f = __expf(m1 - mn1);
        m0 = mn0; m1 = mn1;

        float rs0 = 0.f, rs1 = 0.f;
        #pragma unroll
        for (int ni = 0; ni < 8; ni++) {
            const float p00 = __expf(s[ni][0] - mn0);
            const float p01 = __expf(s[ni][1] - mn0);
            const float p10 = __expf(s[ni][2] - mn1);
            const float p11 = __expf(s[ni][3] - mn1);
            rs0 += p00 + p01; rs1 += p10 + p11;
            float2 w0; w0.x = p00; w0.y = p01;
            float2 w1; w1.x = p10; w1.y = p11;
            *(float2*)(Ps + qrow * AQ + ni * 8 + tq * 2)       = w0;
            *(float2*)(Ps + (qrow + 8) * AQ + ni * 8 + tq * 2) = w1;
        }
        rs0 += __shfl_xor_sync(0xffffffffu, rs0, 1);
        rs0 += __shfl_xor_sync(0xffffffffu, rs0, 2);
        rs1 += __shfl_xor_sync(0xffffffffu, rs1, 1);
        rs1 += __shfl_xor_sync(0xffffffffu, rs1, 2);
        l0 = l0 * c0f + rs0;
        l1 = l1 * c1f + rs1;

        #pragma unroll
        for (int ni = 0; ni < 8; ni++) {
            o[ni][0] *= c0f; o[ni][1] *= c0f;
            o[ni][2] *= c1f; o[ni][3] *= c1f;
        }
        __syncwarp();                    // Ps rows are warp-local

        // O += P @ V
        #pragma unroll
        for (int kk = 0; kk < 8; kk++) {
            const int k0 = kk * 8;
            uint32_t a[4];
            a[0] = f2tf(Ps[qrow * AQ + k0 + tq]);
            a[1] = f2tf(Ps[(qrow + 8) * AQ + k0 + tq]);
            a[2] = f2tf(Ps[qrow * AQ + k0 + tq + 4]);
            a[3] = f2tf(Ps[(qrow + 8) * AQ + k0 + tq + 4]);
            #pragma unroll
            for (int ni = 0; ni < 8; ni++) {
                uint32_t bb[2];
                bb[0] = f2tf(Vs[(k0 + tq) * AQ + ni * 8 + gid]);
                bb[1] = f2tf(Vs[(k0 + tq + 4) * AQ + ni * 8 + gid]);
                mma_tf32(o[ni], a, bb);
            }
        }
    }

    const float i0 = 1.f / l0, i1 = 1.f / l1;
    float* op0 = ctx + ((size_t)(b * SEQ) + grow0) * (NHEAD * HDIM) + h * HDIM;
    float* op1 = ctx + ((size_t)(b * SEQ) + grow1) * (NHEAD * HDIM) + h * HDIM;
    #pragma unroll
    for (int ni = 0; ni < 8; ni++) {
        float2 v0; v0.x = o[ni][0] * i0; v0.y = o[ni][1] * i0;
        float2 v1; v1.x = o[ni][2] * i1; v1.y = o[ni][3] * i1;
        *(float2*)(op0 + ni * 8 + tq * 2) = v0;
        *(float2*)(op1 + ni * 8 + tq * 2) = v1;
    }
}

// ---------------------------------------------------------------------------
// Host: tensormap encoding via runtime-resolved driver entry point
// ---------------------------------------------------------------------------
typedef CUresult (*PFN_encodeTiled)(
    CUtensorMap*, CUtensorMapDataType, cuuint32_t, void*,
    const cuuint64_t*, const cuuint64_t*, const cuuint32_t*, const cuuint32_t*,
    CUtensorMapInterleave, CUtensorMapSwizzle, CUtensorMapL2promotion,
    CUtensorMapFloatOOBfill);

static void encode2d(PFN_encodeTiled fn, CUtensorMap* tm,
                     const void* gptr, uint64_t inner, uint64_t outer)
{
    cuuint64_t dims[2]    = {inner, outer};
    cuuint64_t strides[1] = {inner * 4};
    cuuint32_t box[2]     = {32u, 128u};
    cuuint32_t es[2]      = {1u, 1u};
    fn(tm, CU_TENSOR_MAP_DATA_TYPE_FLOAT32, 2, (void*)gptr,
       dims, strides, box, es,
       CU_TENSOR_MAP_INTERLEAVE_NONE, CU_TENSOR_MAP_SWIZZLE_128B,
       CU_TENSOR_MAP_L2_PROMOTION_L2_128B, CU_TENSOR_MAP_FLOAT_OOB_FILL_NONE);
}

extern "C" void kernel_launch(void* const* d_in, const int* in_sizes, int n_in,
                              void* d_out, int out_size)
{
    const float* x     = (const float*)d_in[0];
    const float* ln_w  = (const float*)d_in[1];
    const float* ln_b  = (const float*)d_in[2];
    const float* wqkv  = (const float*)d_in[3];
    const float* bqkv  = (const float*)d_in[4];
    const float* wout  = (const float*)d_in[5];
    const float* bout  = (const float*)d_in[6];
    const float* fc1_w = (const float*)d_in[7];
    const float* fc1_b = (const float*)d_in[8];
    const float* fc2_w = (const float*)d_in[9];
    const float* fc2_b = (const float*)d_in[10];
    float* out = (float*)d_out;

    float *h, *qkv, *ctx, *attn, *ff;
    cudaGetSymbolAddress((void**)&h,    g_h);
    cudaGetSymbolAddress((void**)&qkv,  g_qkv);
    cudaGetSymbolAddress((void**)&ctx,  g_ctx);
    cudaGetSymbolAddress((void**)&attn, g_attn);
    cudaGetSymbolAddress((void**)&ff,   g_ff);

    void* fnp = nullptr;
    cudaDriverEntryPointQueryResult qres;
    cudaGetDriverEntryPoint("cuTensorMapEncodeTiled", &fnp,
                            cudaEnableDefault, &qres);
    PFN_encodeTiled enc = (PFN_encodeTiled)fnp;

    CUtensorMap tm_h, tm_wqkv, tm_ctx, tm_wout, tm_fc1, tm_ff, tm_fc2;
    encode2d(enc, &tm_h,    h,     D_MODEL, T_TOK);
    encode2d(enc, &tm_wqkv, wqkv,  D_MODEL, QKV_N);
    encode2d(enc, &tm_ctx,  ctx,   D_MODEL, T_TOK);
    encode2d(enc, &tm_wout, wout,  D_MODEL, D_MODEL);
    encode2d(enc, &tm_fc1,  fc1_w, D_MODEL, FF_N);
    encode2d(enc, &tm_ff,   ff,    FF_N,    T_TOK);
    encode2d(enc, &tm_fc2,  fc2_w, FF_N,    D_MODEL);

    cudaFuncSetAttribute(hmma_gemm<0>, cudaFuncAttributeMaxDynamicSharedMemorySize, GSMEM);
    cudaFuncSetAttribute(hmma_gemm<1>, cudaFuncAttributeMaxDynamicSharedMemorySize, GSMEM);
    cudaFuncSetAttribute(hmma_gemm<2>, cudaFuncAttributeMaxDynamicSharedMemorySize, GSMEM);
    cudaFuncSetAttribute(attn_mma_kernel, cudaFuncAttributeMaxDynamicSharedMemorySize, ASMEM);

    // Lazy one-time side stream + fork/join events (created on the first,
    // uncaptured correctness call; reused by every later call so the
    // captured graph sees identical work each time). No device allocation.
    static cudaStream_t s2 = nullptr;
    static cudaEvent_t evFork = nullptr, evJoin = nullptr;
    if (s2 == nullptr) {
        cudaStreamCreateWithFlags(&s2, cudaStreamNonBlocking);
        cudaEventCreateWithFlags(&evFork, cudaEventDisableTiming);
        cudaEventCreateWithFlags(&evJoin, cudaEventDisableTiming);
    }

    // 1. LayerNorm (main stream)
    ln_kernel<<<T_TOK, 256>>>(x, ln_w, ln_b, h);

    // Fork: FC1 (depends only on h) runs on s2 concurrently with the
    // attention chain on the main stream.
    cudaEventRecord(evFork, 0);
    cudaStreamWaitEvent(s2, evFork, 0);

    // -- side stream: FC1 + GELU --
    hmma_gemm<1><<<dim3(FF_N / 128, T_TOK / 128), 128, GSMEM, s2>>>(
        tm_h, tm_fc1, fc1_b, ff, nullptr, nullptr, FF_N, D_MODEL);
    cudaEventRecord(evJoin, s2);

    // -- main stream: attention chain --
    // 2. QKV projection
    hmma_gemm<0><<<dim3(QKV_N / 128, T_TOK / 128), 128, GSMEM>>>(
        tm_h, tm_wqkv, bqkv, qkv, nullptr, nullptr, QKV_N, D_MODEL);

    // 3. RoPE
    rope_kernel<<<(T_TOK * 40 * 16 + 255) / 256, 256>>>(qkv);

    // 4. Attention (tf32 MMA flash)
    attn_mma_kernel<<<dim3(SEQ / 64, NHEAD, 2), 128, ASMEM>>>(qkv, ctx);

    // 5. Out projection
    hmma_gemm<0><<<dim3(D_MODEL / 128, T_TOK / 128), 128, GSMEM>>>(
        tm_ctx, tm_wout, bout, attn, nullptr, nullptr, D_MODEL, D_MODEL);

    // Join: FC2 needs ff (side stream) + attn residual (main stream).
    cudaStreamWaitEvent(0, evJoin, 0);

    // 6. FC2 + residuals (attn_out + x)
    hmma_gemm<2><<<dim3(D_MODEL / 128, T_TOK / 128), 128, GSMEM>>>(
        tm_ff, tm_fc2, fc2_b, out, attn, x, D_MODEL, FF_N);
}